// round 11
// baseline (speedup 1.0000x reference)
#include <cuda_runtime.h>
#include <math.h>

#define N_NODES 50000
#define N_EDGES 800000
#define ET      (N_EDGES + N_NODES)   /* edges + self loops = 850000 */
#define FDIM    128
#define NHEAD   4
#define NCLS    40
#define NEG_SLOPE 0.2f

typedef unsigned long long ull;

// -------------------- scratch (device globals; no runtime alloc) ------------
__device__ float g_xh  [(size_t)N_NODES * FDIM];   // transformed features (per layer)
__device__ float g_h   [(size_t)N_NODES * FDIM];   // layer output / next input
__device__ float g_asrc[N_NODES * NHEAD];
__device__ float g_adst[N_NODES * NHEAD];
__device__ int2  g_edge [ET];                      // packed (src,dst) incl. self loops
__device__ int   g_count[N_NODES];                 // in-degree histogram
__device__ int   g_rowptr[N_NODES + 1];            // CSR row pointers (by dst)
__device__ int   g_cursor[N_NODES];                // scatter cursors
__device__ int   g_csrc [ET];                      // CSR: src list grouped by dst
__device__ int   g_is64;

// -------------------- packed f32x2 helpers ----------------------------------
__device__ __forceinline__ ull pack2(float v) {
    ull r; unsigned u = __float_as_uint(v);
    asm("mov.b64 %0, {%1, %2};" : "=l"(r) : "r"(u), "r"(u));
    return r;
}
__device__ __forceinline__ ull fma2(ull a, ull b, ull c) {
    ull r;
    asm("fma.rn.f32x2 %0, %1, %2, %3;" : "=l"(r) : "l"(a), "l"(b), "l"(c));
    return r;
}
__device__ __forceinline__ void unpack2(ull v, float& lo, float& hi) {
    unsigned a, b;
    asm("mov.b64 {%0, %1}, %2;" : "=r"(a), "=r"(b) : "l"(v));
    lo = __uint_as_float(a); hi = __uint_as_float(b);
}

// -------------------- edge prep: dtype detect + pack + histogram ------------
// int64 iff the high 32-bit words of the first 256 values are ALL zero
// (P[misdetect | int32] = (1/N_NODES)^256 ~= 0; int64 ids < 2^31 -> always 0).
__global__ void detect_kernel(const void* ei) {
    if (threadIdx.x == 0 && blockIdx.x == 0) {
        const int* p = (const int*)ei;
        int all_zero = 1;
        for (int i = 0; i < 256; i++)
            if (p[2 * i + 1] != 0) { all_zero = 0; break; }
        g_is64 = all_zero;
    }
}

__global__ void convert_hist_kernel(const void* __restrict__ ei) {
    const int e = blockIdx.x * blockDim.x + threadIdx.x;
    if (e >= ET) return;
    int s, d;
    if (e < N_EDGES) {
        if (g_is64) {
            const long long* p = (const long long*)ei;
            s = (int)p[e];
            d = (int)p[N_EDGES + e];
        } else {
            const int* p = (const int*)ei;
            s = p[e];
            d = p[N_EDGES + e];
        }
    } else {
        s = d = e - N_EDGES;   // self loop
    }
    g_edge[e] = make_int2(s, d);
    atomicAdd(&g_count[d], 1);
}

// single-block exclusive scan of g_count -> g_rowptr AND g_cursor
// (shfl scan, 4 elem/thread; cursor write fused to avoid a graph memcpy node)
__global__ __launch_bounds__(1024) void scan_kernel() {
    __shared__ int wsum[32];
    const int tid = threadIdx.x, lane = tid & 31, wid = tid >> 5;
    int carry = 0;
    for (int base = 0; base < N_NODES; base += 4096) {
        const int i0 = base + tid * 4;
        int v0 = (i0 + 0 < N_NODES) ? g_count[i0 + 0] : 0;
        int v1 = (i0 + 1 < N_NODES) ? g_count[i0 + 1] : 0;
        int v2 = (i0 + 2 < N_NODES) ? g_count[i0 + 2] : 0;
        int v3 = (i0 + 3 < N_NODES) ? g_count[i0 + 3] : 0;
        const int tot = v0 + v1 + v2 + v3;
        int incl = tot;
        #pragma unroll
        for (int off = 1; off < 32; off <<= 1) {
            int n = __shfl_up_sync(0xFFFFFFFFu, incl, off);
            if (lane >= off) incl += n;
        }
        if (lane == 31) wsum[wid] = incl;
        __syncthreads();
        if (wid == 0) {
            int w = wsum[lane];
            #pragma unroll
            for (int off = 1; off < 32; off <<= 1) {
                int n = __shfl_up_sync(0xFFFFFFFFu, w, off);
                if (lane >= off) w += n;
            }
            wsum[lane] = w;
        }
        __syncthreads();
        const int batch_total = wsum[31];
        const int woff = (wid > 0) ? wsum[wid - 1] : 0;
        int excl = carry + woff + incl - tot;
        if (i0 + 0 < N_NODES) { g_rowptr[i0 + 0] = excl; g_cursor[i0 + 0] = excl; }
        excl += v0;
        if (i0 + 1 < N_NODES) { g_rowptr[i0 + 1] = excl; g_cursor[i0 + 1] = excl; }
        excl += v1;
        if (i0 + 2 < N_NODES) { g_rowptr[i0 + 2] = excl; g_cursor[i0 + 2] = excl; }
        excl += v2;
        if (i0 + 3 < N_NODES) { g_rowptr[i0 + 3] = excl; g_cursor[i0 + 3] = excl; }
        carry += batch_total;
        __syncthreads();
    }
    if (tid == 0) g_rowptr[N_NODES] = carry;   // == ET
}

__global__ void scatter_kernel() {
    const int e = blockIdx.x * blockDim.x + threadIdx.x;
    if (e >= ET) return;
    int2 ed = g_edge[e];
    int pos = atomicAdd(&g_cursor[ed.y], 1);
    g_csrc[pos] = ed.x;
}

// ---- GEMM C[N,128] = A[N,128] @ B[128,128], fused attention-dot epilogue ----
// 128x128 block tile, 256 threads, each thread 8 rows x 8 cols, FFMA2 inner.
// FFMA2-pipe-bound by model (~24us); smem traffic is below the pipe floor.
__global__ __launch_bounds__(256) void gemm_attn_kernel(
    const float* __restrict__ A, const float* __restrict__ B,
    const float* __restrict__ attS, const float* __restrict__ attD,
    float* __restrict__ C)
{
    __shared__ float As[128][33];     // broadcast scalar reads, conflict-free
    __shared__ float Bs[32][128];
    const int tid = threadIdx.x;
    const int ty  = tid >> 4;         // 0..15 -> 8 rows each
    const int tx  = tid & 15;         // 0..15 -> 8 cols each
    const int row0 = blockIdx.x * 128;

    ull acc2[8][4];
    #pragma unroll
    for (int i = 0; i < 8; i++)
        #pragma unroll
        for (int p = 0; p < 4; p++) acc2[i][p] = 0ull;

    for (int k0 = 0; k0 < FDIM; k0 += 32) {
        #pragma unroll
        for (int t = 0; t < 4; t++) {       // A tile 128x32
            int idx = tid + t * 256;
            int r = idx >> 3;
            int c = (idx & 7) << 2;
            float4 v = make_float4(0.f, 0.f, 0.f, 0.f);
            int gr = row0 + r;
            if (gr < N_NODES)
                v = *(const float4*)&A[(size_t)gr * FDIM + k0 + c];
            As[r][c + 0] = v.x; As[r][c + 1] = v.y;
            As[r][c + 2] = v.z; As[r][c + 3] = v.w;
        }
        #pragma unroll
        for (int t = 0; t < 4; t++) {       // B tile 32x128
            int idx = tid + t * 256;
            int r = idx >> 5;
            int c = (idx & 31) << 2;
            *(float4*)&Bs[r][c] = *(const float4*)&B[(size_t)(k0 + r) * FDIM + c];
        }
        __syncthreads();

        #pragma unroll
        for (int k = 0; k < 32; k++) {
            ulonglong2 bb0 = *(const ulonglong2*)&Bs[k][tx * 8];
            ulonglong2 bb1 = *(const ulonglong2*)&Bs[k][tx * 8 + 4];
            #pragma unroll
            for (int i = 0; i < 8; i++) {
                ull ap = pack2(As[ty * 8 + i][k]);
                acc2[i][0] = fma2(ap, bb0.x, acc2[i][0]);
                acc2[i][1] = fma2(ap, bb0.y, acc2[i][1]);
                acc2[i][2] = fma2(ap, bb1.x, acc2[i][2]);
                acc2[i][3] = fma2(ap, bb1.y, acc2[i][3]);
            }
        }
        __syncthreads();
    }

    const float4 s0 = *(const float4*)&attS[tx * 8];
    const float4 s1 = *(const float4*)&attS[tx * 8 + 4];
    const float4 d0 = *(const float4*)&attD[tx * 8];
    const float4 d1 = *(const float4*)&attD[tx * 8 + 4];
    const int h = tx >> 2;            // this thread's 8 cols all in head tx/4

    #pragma unroll
    for (int i = 0; i < 8; i++) {
        const int row = row0 + ty * 8 + i;
        float c0, c1, c2, c3, c4, c5, c6, c7;
        unpack2(acc2[i][0], c0, c1);
        unpack2(acc2[i][1], c2, c3);
        unpack2(acc2[i][2], c4, c5);
        unpack2(acc2[i][3], c6, c7);
        if (row < N_NODES) {
            *(float4*)&C[(size_t)row * FDIM + tx * 8 + 0] = make_float4(c0, c1, c2, c3);
            *(float4*)&C[(size_t)row * FDIM + tx * 8 + 4] = make_float4(c4, c5, c6, c7);
        }
        float ps = c0 * s0.x + c1 * s0.y + c2 * s0.z + c3 * s0.w
                 + c4 * s1.x + c5 * s1.y + c6 * s1.z + c7 * s1.w;
        float pd = c0 * d0.x + c1 * d0.y + c2 * d0.z + c3 * d0.w
                 + c4 * d1.x + c5 * d1.y + c6 * d1.z + c7 * d1.w;
        ps += __shfl_xor_sync(0xFFFFFFFFu, ps, 1);
        ps += __shfl_xor_sync(0xFFFFFFFFu, ps, 2);
        pd += __shfl_xor_sync(0xFFFFFFFFu, pd, 1);
        pd += __shfl_xor_sync(0xFFFFFFFFu, pd, 2);
        if (row < N_NODES && (tx & 3) == 0) {
            g_asrc[row * NHEAD + h] = ps;
            g_adst[row * NHEAD + h] = pd;
        }
    }
}

// -------- fused gather: softmax (no-shift) + aggregate + bias + relu --------
// One warp per destination node; lane covers channels [4*lane, 4*lane+4).
// Every lane computes exp for ITS OWN head (MUFU ~free at 1 warp-instr/edge),
// so den is replicated within each 8-lane head group -> no reductions needed.
// 4-wide manual unroll gives MLP=4 on the 128B xh gathers (L2-resident).
__global__ __launch_bounds__(256) void gather_agg_kernel(
    const float* __restrict__ xh, const float* __restrict__ bias,
    float* __restrict__ out)
{
    const int lane = threadIdx.x & 31;
    const int d = (blockIdx.x * blockDim.x + threadIdx.x) >> 5;
    if (d >= N_NODES) return;

    const int beg = g_rowptr[d];
    const int end = g_rowptr[d + 1];
    const int hh = lane >> 3;                    // head owning this lane's channels
    const float adst = g_adst[d * NHEAD + hh];

    float den = 0.0f;
    float4 acc = make_float4(0.f, 0.f, 0.f, 0.f);

    for (int j0 = beg; j0 < end; j0 += 32) {
        const int jn = min(32, end - j0);
        int s_l = (lane < jn) ? g_csrc[j0 + lane] : 0;
        int t = 0;
        for (; t + 4 <= jn; t += 4) {
            const int sa = __shfl_sync(0xFFFFFFFFu, s_l, t + 0);
            const int sb = __shfl_sync(0xFFFFFFFFu, s_l, t + 1);
            const int sc = __shfl_sync(0xFFFFFFFFu, s_l, t + 2);
            const int sd = __shfl_sync(0xFFFFFFFFu, s_l, t + 3);
            const float aa = g_asrc[sa * NHEAD + hh];
            const float ab = g_asrc[sb * NHEAD + hh];
            const float ac = g_asrc[sc * NHEAD + hh];
            const float ad = g_asrc[sd * NHEAD + hh];
            const float4 va = *(const float4*)&xh[(size_t)sa * FDIM + lane * 4];
            const float4 vb = *(const float4*)&xh[(size_t)sb * FDIM + lane * 4];
            const float4 vc = *(const float4*)&xh[(size_t)sc * FDIM + lane * 4];
            const float4 vd = *(const float4*)&xh[(size_t)sd * FDIM + lane * 4];
            float la = aa + adst; la = fmaxf(la, NEG_SLOPE * la);
            float lb = ab + adst; lb = fmaxf(lb, NEG_SLOPE * lb);
            float lc = ac + adst; lc = fmaxf(lc, NEG_SLOPE * lc);
            float ld = ad + adst; ld = fmaxf(ld, NEG_SLOPE * ld);
            const float ea = __expf(la);   // no max-shift: logits are O(5)
            const float eb = __expf(lb);
            const float ec = __expf(lc);
            const float ed = __expf(ld);
            den += ea + eb + ec + ed;
            acc.x = fmaf(va.x, ea, fmaf(vb.x, eb, fmaf(vc.x, ec, fmaf(vd.x, ed, acc.x))));
            acc.y = fmaf(va.y, ea, fmaf(vb.y, eb, fmaf(vc.y, ec, fmaf(vd.y, ed, acc.y))));
            acc.z = fmaf(va.z, ea, fmaf(vb.z, eb, fmaf(vc.z, ec, fmaf(vd.z, ed, acc.z))));
            acc.w = fmaf(va.w, ea, fmaf(vb.w, eb, fmaf(vc.w, ec, fmaf(vd.w, ed, acc.w))));
        }
        for (; t < jn; t++) {
            const int s = __shfl_sync(0xFFFFFFFFu, s_l, t);
            const float a = g_asrc[s * NHEAD + hh];
            const float4 v = *(const float4*)&xh[(size_t)s * FDIM + lane * 4];
            float l = a + adst; l = fmaxf(l, NEG_SLOPE * l);
            const float e = __expf(l);
            den += e;
            acc.x = fmaf(v.x, e, acc.x);
            acc.y = fmaf(v.y, e, acc.y);
            acc.z = fmaf(v.z, e, acc.z);
            acc.w = fmaf(v.w, e, acc.w);
        }
    }

    const float inv = 1.0f / (den + 1e-16f);
    const float4 b = *(const float4*)&bias[lane * 4];
    float4 r;
    r.x = fmaxf(fmaf(acc.x, inv, b.x), 0.f);
    r.y = fmaxf(fmaf(acc.y, inv, b.y), 0.f);
    r.z = fmaxf(fmaf(acc.z, inv, b.z), 0.f);
    r.w = fmaxf(fmaf(acc.w, inv, b.w), 0.f);
    *(float4*)&out[(size_t)d * FDIM + lane * 4] = r;
}

// -------- classifier: logits = h@Wc + bc, then row log_softmax --------------
// 256 threads / block = 32 nodes x 8 threads; FFMA2 inner product.
__global__ __launch_bounds__(256) void classifier_kernel(
    const float* __restrict__ h, const float* __restrict__ Wc,
    const float* __restrict__ bc, float* __restrict__ out)
{
    __shared__ float WcT[NCLS][FDIM];   // rows 512B-aligned
    __shared__ float bcs[NCLS];
    const int tid = threadIdx.x;
    for (int i = tid; i < FDIM * NCLS; i += 256) {
        int k = i / NCLS, c = i % NCLS;
        WcT[c][k] = Wc[i];
    }
    if (tid < NCLS) bcs[tid] = bc[tid];
    __syncthreads();

    const int grp = tid >> 3;            // local node 0..31
    const int j   = tid & 7;             // sub-lane within node group
    const int n   = blockIdx.x * 32 + grp;
    const bool valid = (n < N_NODES);
    const int nn = valid ? n : 0;

    // 16 features per thread as 8 packed f32x2 (8B-aligned: even float offsets)
    ull h2[8];
    #pragma unroll
    for (int q = 0; q < 8; q++)
        h2[q] = *(const ull*)&h[(size_t)nn * FDIM + j * 16 + q * 2];

    float logit[NCLS];
    #pragma unroll
    for (int c = 0; c < NCLS; c++) {
        ull a = 0ull;
        #pragma unroll
        for (int q = 0; q < 8; q++) {
            ull w = *(const ull*)&WcT[c][j * 16 + q * 2];
            a = fma2(h2[q], w, a);
        }
        float lo, hi;
        unpack2(a, lo, hi);
        logit[c] = lo + hi;
    }
    #pragma unroll
    for (int c = 0; c < NCLS; c++) {
        logit[c] += __shfl_xor_sync(0xFFFFFFFFu, logit[c], 1);
        logit[c] += __shfl_xor_sync(0xFFFFFFFFu, logit[c], 2);
        logit[c] += __shfl_xor_sync(0xFFFFFFFFu, logit[c], 4);
        logit[c] += bcs[c];
    }
    float mx = -INFINITY;
    #pragma unroll
    for (int c = 0; c < NCLS; c++) mx = fmaxf(mx, logit[c]);
    float se = 0.f;
    #pragma unroll
    for (int c = 0; c < NCLS; c++) se += __expf(logit[c] - mx);
    float lse = mx + logf(se);

    if (valid) {
        const int base = j * 5;
        #pragma unroll
        for (int c = 0; c < NCLS; c++)        // compile-time register index,
            if ((unsigned)(c - base) < 5u)    // runtime predicate -> no spill
                out[(size_t)n * NCLS + c] = logit[c] - lse;
    }
}

// ---------------------------------------------------------------------------
extern "C" void kernel_launch(void* const* d_in, const int* in_sizes, int n_in,
                              void* d_out, int out_size) {
    const float* x   = (const float*)d_in[0];
    const void*  ei  = d_in[1];
    const float* W1  = (const float*)d_in[2];
    const float* as1 = (const float*)d_in[3];
    const float* ad1 = (const float*)d_in[4];
    const float* b1  = (const float*)d_in[5];
    const float* W2  = (const float*)d_in[6];
    const float* as2 = (const float*)d_in[7];
    const float* ad2 = (const float*)d_in[8];
    const float* b2  = (const float*)d_in[9];
    const float* Wc  = (const float*)d_in[10];
    const float* bc  = (const float*)d_in[11];
    float* out = (float*)d_out;

    float *p_xh, *p_h;
    int   *p_count;
    cudaGetSymbolAddress((void**)&p_xh,    g_xh);
    cudaGetSymbolAddress((void**)&p_h,     g_h);
    cudaGetSymbolAddress((void**)&p_count, g_count);

    const int GEMM_GRID = (N_NODES + 127) / 128;
    const int GA_GRID   = (N_NODES + 7) / 8;     // warp/node, 256 threads
    const int E_GRID    = (ET + 255) / 256;

    // ---- CSR build (once per call; reused by both layers; re-inited so the
    //      captured graph is replay-deterministic) ----
    cudaMemsetAsync(p_count, 0, N_NODES * sizeof(int));
    detect_kernel<<<1, 32>>>(ei);
    convert_hist_kernel<<<E_GRID, 256>>>(ei);
    scan_kernel<<<1, 1024>>>();                  // writes rowptr AND cursor
    scatter_kernel<<<E_GRID, 256>>>();

    // ---- layer 1 ----
    gemm_attn_kernel<<<GEMM_GRID, 256>>>(x, W1, as1, ad1, p_xh);
    gather_agg_kernel<<<GA_GRID, 256>>>(p_xh, b1, p_h);

    // ---- layer 2 ----
    gemm_attn_kernel<<<GEMM_GRID, 256>>>(p_h, W2, as2, ad2, p_xh);
    gather_agg_kernel<<<GA_GRID, 256>>>(p_xh, b2, p_h);

    // ---- classifier + log_softmax ----
    classifier_kernel<<<(N_NODES + 31) / 32, 256>>>(p_h, Wc, bc, out);
}